// round 5
// baseline (speedup 1.0000x reference)
#include <cuda_runtime.h>
#include <mma.h>
#include <math.h>
#include <stdint.h>

using namespace nvcuda;

// ---------------- constants ----------------
#define T_FR   8
#define NSEQ   197
#define NTOK   1576
#define DMODEL 768
#define NHEAD  12
#define DHEAD  64
#define DMLP   3072
#define QKVW   2304
#define NPAT   196
#define SCALE_ 0.125f

// ---------------- scratch ----------------
#define WS_PATCH   0
#define WS_EMB     (WS_PATCH + 1204224)
#define WS_H       (WS_EMB + 1204224)
#define WS_A       (WS_H + 1210368)
#define WS_QKV     (WS_A + 1210368)
#define WS_SCORES  (WS_QKV + 3631104)
#define WS_O       (WS_SCORES + 29806512)
#define WS_MLP     (WS_O + 1210368)
#define WS_VMEAN   (WS_MLP + 4841472)
#define WS_TOTAL   (WS_VMEAN + 6144)

__device__ float g_ws[WS_TOTAL];

// ---------------- patch gather ----------------
__global__ void gather_patches(const float* __restrict__ x, float* __restrict__ P) {
    int idx = blockIdx.x * 256 + threadIdx.x;
    if (idx >= 1568 * 768) return;
    int m = idx / 768, k = idx - m * 768;
    int t = m / NPAT, p = m - t * NPAT;
    int hp = p / 14, wp = p - hp * 14;
    int c = k >> 8;
    int r = (k >> 4) & 15;
    int j = k & 15;
    P[idx] = x[(((size_t)(t * 3 + c) * 224) + hp * 16 + r) * 224 + wp * 16 + j];
}

// ---------------- token assembly (torch axis scramble) ----------------
__global__ void assemble_h(const float* __restrict__ emb, const float* __restrict__ cls,
                           const float* __restrict__ pos, float* __restrict__ h) {
    int idx = blockIdx.x * 256 + threadIdx.x;
    if (idx >= NTOK * DMODEL) return;
    int s = idx / DMODEL, d = idx - s * DMODEL;
    int t = s / NSEQ, n = s - t * NSEQ;
    float v;
    if (n == 0) {
        v = cls[d];
    } else {
        int l = (n - 1) * DMODEL + d;
        int dsrc = l / NPAT;
        int psrc = l - dsrc * NPAT;
        v = emb[((size_t)t * NPAT + psrc) * DMODEL + dsrc];
    }
    h[idx] = v + pos[n * DMODEL + d];
}

// ================= TF32 tensor-core GEMM core =================
// BM=128, BN=128, BK=32, 256 threads = 8 warps (2x4), warp tile 64x32,
// wmma m16n16k8 tf32. Epilogue staged through smem with bias/res/addvec/GELU.
#define BM 128
#define BN 128
#define BK 32
#define SMEM_GEMM_BYTES (128 * 132 * 4)   // epilogue staging (>= As+Bs = 32KB)

template<bool TRANSB, int EPI>
__device__ __forceinline__ void gemm_core(
    const float* __restrict__ A, int lda,
    const float* __restrict__ B, int ldb,
    const float* __restrict__ bias, const float* __restrict__ res,
    float* __restrict__ C, int ldc,
    int M, int N, int K, int row0, int col0,
    const float* __restrict__ addvec)
{
    extern __shared__ float sm[];
    float* As = sm;                // [BM][BK] row-major
    float* Bs = sm + BM * BK;      // !TRANSB: [BK][BN] row-major ; TRANSB: [BN][BK]
    const int tid = threadIdx.x;
    const int warp = tid >> 5;
    const int wm = warp >> 2;      // 0..1
    const int wn = warp & 3;       // 0..3

    wmma::fragment<wmma::accumulator, 16, 16, 8, float> acc[4][2];
#pragma unroll
    for (int m = 0; m < 4; m++)
#pragma unroll
        for (int n = 0; n < 2; n++)
            wmma::fill_fragment(acc[m][n], 0.0f);

    for (int k0 = 0; k0 < K; k0 += BK) {
        // load A tile (128x32), coalesced over k
#pragma unroll
        for (int it = 0; it < 16; it++) {
            int idx = it * 256 + tid;
            int r = idx >> 5, c = idx & 31;
            int gr = row0 + r, gk = k0 + c;
            float v = (gr < M && gk < K) ? A[(size_t)gr * lda + gk] : 0.0f;
            As[idx] = wmma::__float_to_tf32(v);
        }
        // load B tile
#pragma unroll
        for (int it = 0; it < 16; it++) {
            int idx = it * 256 + tid;
            float v;
            if (TRANSB) {
                int n = idx >> 5, c = idx & 31;
                int gn = col0 + n, gk = k0 + c;
                v = (gn < N && gk < K) ? B[(size_t)gn * ldb + gk] : 0.0f;
            } else {
                int r = idx >> 7, c = idx & 127;
                int gk = k0 + r, gn = col0 + c;
                v = (gk < K && gn < N) ? B[(size_t)gk * ldb + gn] : 0.0f;
            }
            Bs[idx] = wmma::__float_to_tf32(v);
        }
        __syncthreads();

#pragma unroll
        for (int kk = 0; kk < BK; kk += 8) {
            wmma::fragment<wmma::matrix_a, 16, 16, 8, wmma::precision::tf32, wmma::row_major> af[4];
#pragma unroll
            for (int m = 0; m < 4; m++)
                wmma::load_matrix_sync(af[m], As + (size_t)(wm * 64 + m * 16) * BK + kk, BK);
            if (TRANSB) {
                wmma::fragment<wmma::matrix_b, 16, 16, 8, wmma::precision::tf32, wmma::col_major> bf[2];
#pragma unroll
                for (int n = 0; n < 2; n++)
                    wmma::load_matrix_sync(bf[n], Bs + (size_t)(wn * 32 + n * 16) * BK + kk, BK);
#pragma unroll
                for (int m = 0; m < 4; m++)
#pragma unroll
                    for (int n = 0; n < 2; n++)
                        wmma::mma_sync(acc[m][n], af[m], bf[n], acc[m][n]);
            } else {
                wmma::fragment<wmma::matrix_b, 16, 16, 8, wmma::precision::tf32, wmma::row_major> bf[2];
#pragma unroll
                for (int n = 0; n < 2; n++)
                    wmma::load_matrix_sync(bf[n], Bs + (size_t)kk * BN + wn * 32 + n * 16, BN);
#pragma unroll
                for (int m = 0; m < 4; m++)
#pragma unroll
                    for (int n = 0; n < 2; n++)
                        wmma::mma_sync(acc[m][n], af[m], bf[n], acc[m][n]);
            }
        }
        __syncthreads();
    }

    // epilogue: stage to smem [128][132], then bounded vector copy
    float* Cs = sm;
#pragma unroll
    for (int m = 0; m < 4; m++)
#pragma unroll
        for (int n = 0; n < 2; n++)
            wmma::store_matrix_sync(Cs + (size_t)(wm * 64 + m * 16) * 132 + (wn * 32 + n * 16),
                                    acc[m][n], 132, wmma::mem_row_major);
    __syncthreads();
#pragma unroll
    for (int it = 0; it < 64; it++) {     // 64*256 = 16384 = full 128x128 tile
        int idx = it * 256 + tid;
        int r = idx >> 7, c = idx & 127;
        int gr = row0 + r, gc = col0 + c;
        if (gr < M && gc < N) {
            float v = Cs[(size_t)r * 132 + c];
            if (bias)   v += bias[gc];
            if (addvec) v += addvec[gc];
            if (res)    v += res[(size_t)gr * ldc + gc];
            if (EPI == 1) v = 0.5f * v * (1.0f + erff(v * 0.70710678118654752f));
            C[(size_t)gr * ldc + gc] = v;
        }
    }
}

template<int EPI>
__global__ void __launch_bounds__(256, 2)
gemm_tf32_k(const float* __restrict__ A, int lda, const float* __restrict__ B, int ldb,
            const float* __restrict__ bias, const float* __restrict__ res,
            float* __restrict__ C, int ldc, int M, int N, int K) {
    gemm_core<false, EPI>(A, lda, B, ldb, bias, res, C, ldc, M, N, K,
                          blockIdx.y * BM, blockIdx.x * BN, nullptr);
}

__global__ void __launch_bounds__(256, 2)
gemm_bt_k(const float* __restrict__ A, int lda, const float* __restrict__ B, int ldb,
          const float* __restrict__ bias, float* __restrict__ C, int ldc,
          int M, int N, int K) {
    gemm_core<true, 0>(A, lda, B, ldb, bias, nullptr, C, ldc, M, N, K,
                       blockIdx.y * BM, blockIdx.x * BN, nullptr);
}

// scores(z) = Q_z @ K_z^T    z = h*nseg + t
__global__ void __launch_bounds__(256, 2)
qk_tf32(const float* __restrict__ qkv, float* __restrict__ scores, int seg, int nseg) {
    int z = blockIdx.z;
    int h = z / nseg, t = z - h * nseg;
    const float* Qb = qkv + (size_t)t * seg * QKVW + h * DHEAD;
    gemm_core<true, 0>(Qb, QKVW, Qb + 768, QKVW, nullptr, nullptr,
                       scores + (size_t)z * seg * seg, seg,
                       seg, seg, DHEAD, blockIdx.y * BM, blockIdx.x * BN, nullptr);
}

// O(z) = P_z @ V_z (+vmean broadcast), writes into o[tok][h*64+c]
__global__ void __launch_bounds__(256, 2)
av_tf32(const float* __restrict__ scores, const float* __restrict__ qkv,
        const float* __restrict__ vmean, float* __restrict__ o, int seg, int nseg) {
    int z = blockIdx.z;
    int h = z / nseg, t = z - h * nseg;
    gemm_core<false, 0>(scores + (size_t)z * seg * seg, seg,
                        qkv + (size_t)t * seg * QKVW + 1536 + h * DHEAD, QKVW,
                        nullptr, nullptr,
                        o + (size_t)t * seg * DMODEL + h * DHEAD, DMODEL,
                        seg, DHEAD, seg, blockIdx.y * BM, 0,
                        vmean ? vmean + (size_t)z * DHEAD : nullptr);
}

// ---------------- softmax (register-cached, 1R + 1W) ----------------
__global__ void softmax_kernel(float* __restrict__ scores, int seg) {
    float* row = scores + (size_t)blockIdx.x * seg;
    const int tid = threadIdx.x;
    __shared__ float sh[8];
    float rv[7];
    int cnt = 0;
    float m = -1e30f;
    for (int i = tid; i < seg; i += 256) {
        float v = row[i];
        rv[cnt++] = v;
        m = fmaxf(m, v);
    }
#pragma unroll
    for (int o = 16; o; o >>= 1) m = fmaxf(m, __shfl_xor_sync(0xffffffffu, m, o));
    if ((tid & 31) == 0) sh[tid >> 5] = m;
    __syncthreads();
    if (tid < 32) {
        float v = (tid < 8) ? sh[tid] : -1e30f;
#pragma unroll
        for (int o = 4; o; o >>= 1) v = fmaxf(v, __shfl_xor_sync(0xffffffffu, v, o));
        if (tid == 0) sh[0] = v;
    }
    __syncthreads();
    m = sh[0];
    __syncthreads();
    float s = 0.f;
#pragma unroll
    for (int j = 0; j < 7; j++) {
        if (j < cnt) {
            float e = __expf((rv[j] - m) * SCALE_);
            rv[j] = e;
            s += e;
        }
    }
#pragma unroll
    for (int o = 16; o; o >>= 1) s += __shfl_xor_sync(0xffffffffu, s, o);
    if ((tid & 31) == 0) sh[tid >> 5] = s;
    __syncthreads();
    if (tid < 32) {
        float v = (tid < 8) ? sh[tid] : 0.f;
#pragma unroll
        for (int o = 4; o; o >>= 1) v += __shfl_xor_sync(0xffffffffu, v, o);
        if (tid == 0) sh[0] = v;
    }
    __syncthreads();
    float inv = 1.0f / sh[0];
    cnt = 0;
    for (int i = tid; i < seg; i += 256) row[i] = rv[cnt++] * inv;
}

// ---------------- V mean per (head, frame) ----------------
__global__ void vmean_kernel(const float* __restrict__ qkv, float* __restrict__ vmean) {
    int z = blockIdx.x;
    int h = z >> 3, t = z & 7;
    int d = threadIdx.x;
    const float* base = qkv + (size_t)t * NSEQ * QKVW + 1536 + h * DHEAD + d;
    float s = 0.f;
    for (int n = 0; n < NSEQ; n++) s += base[(size_t)n * QKVW];
    vmean[z * DHEAD + d] = s * (1.0f / (float)NSEQ);
}

// ---------------- LayerNorm over 768, float4 (192 threads) ----------------
__global__ void layernorm_kernel(const float* __restrict__ X, const float* __restrict__ g,
                                 const float* __restrict__ b, float* __restrict__ Y) {
    const int row = blockIdx.x;
    const int tid = threadIdx.x;   // 0..191
    __shared__ float sh[8];
    float4 v = *(const float4*)(X + (size_t)row * DMODEL + tid * 4);
    float s = v.x + v.y + v.z + v.w;
#pragma unroll
    for (int o = 16; o; o >>= 1) s += __shfl_xor_sync(0xffffffffu, s, o);
    if ((tid & 31) == 0) sh[tid >> 5] = s;
    __syncthreads();
    if (tid < 32) {
        float t2 = (tid < 6) ? sh[tid] : 0.f;
#pragma unroll
        for (int o = 4; o; o >>= 1) t2 += __shfl_xor_sync(0xffffffffu, t2, o);
        if (tid == 0) sh[0] = t2;
    }
    __syncthreads();
    float mu = sh[0] * (1.0f / (float)DMODEL);
    __syncthreads();
    float dx = v.x - mu, dy = v.y - mu, dz = v.z - mu, dw = v.w - mu;
    s = dx * dx + dy * dy + dz * dz + dw * dw;
#pragma unroll
    for (int o = 16; o; o >>= 1) s += __shfl_xor_sync(0xffffffffu, s, o);
    if ((tid & 31) == 0) sh[tid >> 5] = s;
    __syncthreads();
    if (tid < 32) {
        float t2 = (tid < 6) ? sh[tid] : 0.f;
#pragma unroll
        for (int o = 4; o; o >>= 1) t2 += __shfl_xor_sync(0xffffffffu, t2, o);
        if (tid == 0) sh[0] = t2;
    }
    __syncthreads();
    float rstd = rsqrtf(sh[0] * (1.0f / (float)DMODEL) + 1e-5f);
    float4 gg = *(const float4*)(g + tid * 4);
    float4 bb = *(const float4*)(b + tid * 4);
    float4 out;
    out.x = dx * rstd * gg.x + bb.x;
    out.y = dy * rstd * gg.y + bb.y;
    out.z = dz * rstd * gg.z + bb.z;
    out.w = dw * rstd * gg.w + bb.w;
    *(float4*)(Y + (size_t)row * DMODEL + tid * 4) = out;
}

// ---------------- launch ----------------
extern "C" void kernel_launch(void* const* d_in, const int* in_sizes, int n_in,
                              void* d_out, int out_size) {
    (void)in_sizes; (void)n_in; (void)out_size;
    float* ws = nullptr;
    cudaGetSymbolAddress((void**)&ws, g_ws);

    float* patch  = ws + WS_PATCH;
    float* emb    = ws + WS_EMB;
    float* h      = ws + WS_H;
    float* a      = ws + WS_A;
    float* qkv    = ws + WS_QKV;
    float* scores = ws + WS_SCORES;
    float* o      = ws + WS_O;
    float* mlp    = ws + WS_MLP;
    float* vmean  = ws + WS_VMEAN;

    const float* x      = (const float*)d_in[0];
    const float* Wp     = (const float*)d_in[1];
    const float* bp     = (const float*)d_in[2];
    const float* cls    = (const float*)d_in[3];
    const float* pos    = (const float*)d_in[4];
    const float* ln1_g  = (const float*)d_in[5];
    const float* ln1_b  = (const float*)d_in[6];
    const float* qkv_w  = (const float*)d_in[7];
    const float* qkv_b  = (const float*)d_in[8];
    const float* proj_w = (const float*)d_in[9];
    const float* proj_b = (const float*)d_in[10];
    const float* ln2_g  = (const float*)d_in[11];
    const float* ln2_b  = (const float*)d_in[12];
    const float* fc1_w  = (const float*)d_in[13];
    const float* fc1_b  = (const float*)d_in[14];
    const float* fc2_w  = (const float*)d_in[15];
    const float* fc2_b  = (const float*)d_in[16];
    const float* lnf_g  = (const float*)d_in[17];
    const float* lnf_b  = (const float*)d_in[18];

    // opt-in >48KB dynamic smem for all GEMM instantiations
    cudaFuncSetAttribute(gemm_tf32_k<0>, cudaFuncAttributeMaxDynamicSharedMemorySize, SMEM_GEMM_BYTES);
    cudaFuncSetAttribute(gemm_tf32_k<1>, cudaFuncAttributeMaxDynamicSharedMemorySize, SMEM_GEMM_BYTES);
    cudaFuncSetAttribute(gemm_bt_k,      cudaFuncAttributeMaxDynamicSharedMemorySize, SMEM_GEMM_BYTES);
    cudaFuncSetAttribute(qk_tf32,        cudaFuncAttributeMaxDynamicSharedMemorySize, SMEM_GEMM_BYTES);
    cudaFuncSetAttribute(av_tf32,        cudaFuncAttributeMaxDynamicSharedMemorySize, SMEM_GEMM_BYTES);

    // patch embed
    gather_patches<<<(1568 * 768 + 255) / 256, 256>>>(x, patch);
    gemm_bt_k<<<dim3(6, 13), 256, SMEM_GEMM_BYTES>>>(patch, 768, Wp, 768, bp, emb, 768,
                                                     1568, 768, 768);
    assemble_h<<<(NTOK * DMODEL + 255) / 256, 256>>>(emb, cls, pos, h);

    for (int i = 0; i < 12; i++) {
        // ---- attention ----
        layernorm_kernel<<<NTOK, 192>>>(h, ln1_g + i * DMODEL, ln1_b + i * DMODEL, a);
        gemm_tf32_k<0><<<dim3(18, 13), 256, SMEM_GEMM_BYTES>>>(
            a, DMODEL, qkv_w + (size_t)i * DMODEL * QKVW, QKVW,
            qkv_b + i * QKVW, nullptr, qkv, QKVW, NTOK, QKVW, DMODEL);

        if ((i & 1) == 0) {
            // divided space-time: spatial attention per frame + V-mean broadcast
            vmean_kernel<<<NHEAD * T_FR, DHEAD>>>(qkv, vmean);
            qk_tf32<<<dim3(2, 2, NHEAD * T_FR), 256, SMEM_GEMM_BYTES>>>(qkv, scores, NSEQ, T_FR);
            softmax_kernel<<<NHEAD * T_FR * NSEQ, 256>>>(scores, NSEQ);
            av_tf32<<<dim3(1, 2, NHEAD * T_FR), 256, SMEM_GEMM_BYTES>>>(scores, qkv, vmean, o, NSEQ, T_FR);
        } else {
            // joint space-time
            qk_tf32<<<dim3(13, 13, NHEAD), 256, SMEM_GEMM_BYTES>>>(qkv, scores, NTOK, 1);
            softmax_kernel<<<NHEAD * NTOK, 256>>>(scores, NTOK);
            av_tf32<<<dim3(1, 13, NHEAD), 256, SMEM_GEMM_BYTES>>>(scores, qkv, nullptr, o, NTOK, 1);
        }
        // h += proj(o)
        gemm_tf32_k<0><<<dim3(6, 13), 256, SMEM_GEMM_BYTES>>>(
            o, DMODEL, proj_w + (size_t)i * DMODEL * DMODEL, DMODEL,
            proj_b + i * DMODEL, h, h, DMODEL, NTOK, DMODEL, DMODEL);

        // ---- mlp ----
        layernorm_kernel<<<NTOK, 192>>>(h, ln2_g + i * DMODEL, ln2_b + i * DMODEL, a);
        gemm_tf32_k<1><<<dim3(24, 13), 256, SMEM_GEMM_BYTES>>>(
            a, DMODEL, fc1_w + (size_t)i * DMODEL * DMLP, DMLP,
            fc1_b + i * DMLP, nullptr, mlp, DMLP, NTOK, DMLP, DMODEL);
        gemm_tf32_k<0><<<dim3(6, 13), 256, SMEM_GEMM_BYTES>>>(
            mlp, DMLP, fc2_w + (size_t)i * DMLP * DMODEL, DMODEL,
            fc2_b + i * DMODEL, h, h, DMODEL, NTOK, DMODEL, DMLP);
    }

    layernorm_kernel<<<NTOK, 192>>>(h, lnf_g, lnf_b, (float*)d_out);
}

// round 6
// speedup vs baseline: 1.0040x; 1.0040x over previous
#include <cuda_runtime.h>
#include <mma.h>
#include <math.h>
#include <stdint.h>

using namespace nvcuda;

// ---------------- constants ----------------
#define T_FR   8
#define NSEQ   197
#define NTOK   1576
#define DMODEL 768
#define NHEAD  12
#define DHEAD  64
#define DMLP   3072
#define QKVW   2304
#define NPAT   196
#define SCALE_ 0.125f

// ---------------- scratch ----------------
#define WS_PATCH   0
#define WS_EMB     (WS_PATCH + 1204224)
#define WS_H       (WS_EMB + 1204224)
#define WS_A       (WS_H + 1210368)
#define WS_QKV     (WS_A + 1210368)
#define WS_SCORES  (WS_QKV + 3631104)
#define WS_O       (WS_SCORES + 29806512)
#define WS_MLP     (WS_O + 1210368)
#define WS_VMEAN   (WS_MLP + 4841472)
#define WS_TOTAL   (WS_VMEAN + 6144)

__device__ float g_ws[WS_TOTAL];

// ---------------- patch gather ----------------
__global__ void gather_patches(const float* __restrict__ x, float* __restrict__ P) {
    int idx = blockIdx.x * 256 + threadIdx.x;
    if (idx >= 1568 * 768) return;
    int m = idx / 768, k = idx - m * 768;
    int t = m / NPAT, p = m - t * NPAT;
    int hp = p / 14, wp = p - hp * 14;
    int c = k >> 8;
    int r = (k >> 4) & 15;
    int j = k & 15;
    P[idx] = x[(((size_t)(t * 3 + c) * 224) + hp * 16 + r) * 224 + wp * 16 + j];
}

// ---------------- token assembly (torch axis scramble) ----------------
__global__ void assemble_h(const float* __restrict__ emb, const float* __restrict__ cls,
                           const float* __restrict__ pos, float* __restrict__ h) {
    int idx = blockIdx.x * 256 + threadIdx.x;
    if (idx >= NTOK * DMODEL) return;
    int s = idx / DMODEL, d = idx - s * DMODEL;
    int t = s / NSEQ, n = s - t * NSEQ;
    float v;
    if (n == 0) {
        v = cls[d];
    } else {
        int l = (n - 1) * DMODEL + d;
        int dsrc = l / NPAT;
        int psrc = l - dsrc * NPAT;
        v = emb[((size_t)t * NPAT + psrc) * DMODEL + dsrc];
    }
    h[idx] = v + pos[n * DMODEL + d];
}

// ================= TF32 tensor-core GEMM core =================
// BM=128, BN=128, BK=32, 256 threads = 8 warps (2x4), warp tile 64x32,
// wmma m16n16k8 tf32. Epilogue staged through smem with bias/res/addvec/GELU.
#define BM 128
#define BN 128
#define BK 32
#define SMEM_GEMM_BYTES (128 * 132 * 4)   // epilogue staging (>= As+Bs = 32KB)

template<bool TRANSB, int EPI>
__device__ __forceinline__ void gemm_core(
    const float* __restrict__ A, int lda,
    const float* __restrict__ B, int ldb,
    const float* __restrict__ bias, const float* __restrict__ res,
    float* __restrict__ C, int ldc,
    int M, int N, int K, int row0, int col0,
    const float* __restrict__ addvec)
{
    extern __shared__ float sm[];
    float* As = sm;                // [BM][BK] row-major
    float* Bs = sm + BM * BK;      // !TRANSB: [BK][BN] row-major ; TRANSB: [BN][BK]
    const int tid = threadIdx.x;
    const int warp = tid >> 5;
    const int wm = warp >> 2;      // 0..1
    const int wn = warp & 3;       // 0..3

    wmma::fragment<wmma::accumulator, 16, 16, 8, float> acc[4][2];
#pragma unroll
    for (int m = 0; m < 4; m++)
#pragma unroll
        for (int n = 0; n < 2; n++)
            wmma::fill_fragment(acc[m][n], 0.0f);

    for (int k0 = 0; k0 < K; k0 += BK) {
        // load A tile (128x32), coalesced over k
#pragma unroll
        for (int it = 0; it < 16; it++) {
            int idx = it * 256 + tid;
            int r = idx >> 5, c = idx & 31;
            int gr = row0 + r, gk = k0 + c;
            float v = (gr < M && gk < K) ? A[(size_t)gr * lda + gk] : 0.0f;
            As[idx] = wmma::__float_to_tf32(v);
        }
        // load B tile
#pragma unroll
        for (int it = 0; it < 16; it++) {
            int idx = it * 256 + tid;
            float v;
            if (TRANSB) {
                int n = idx >> 5, c = idx & 31;
                int gn = col0 + n, gk = k0 + c;
                v = (gn < N && gk < K) ? B[(size_t)gn * ldb + gk] : 0.0f;
            } else {
                int r = idx >> 7, c = idx & 127;
                int gk = k0 + r, gn = col0 + c;
                v = (gk < K && gn < N) ? B[(size_t)gk * ldb + gn] : 0.0f;
            }
            Bs[idx] = wmma::__float_to_tf32(v);
        }
        __syncthreads();

#pragma unroll
        for (int kk = 0; kk < BK; kk += 8) {
            wmma::fragment<wmma::matrix_a, 16, 16, 8, wmma::precision::tf32, wmma::row_major> af[4];
#pragma unroll
            for (int m = 0; m < 4; m++)
                wmma::load_matrix_sync(af[m], As + (size_t)(wm * 64 + m * 16) * BK + kk, BK);
            if (TRANSB) {
                wmma::fragment<wmma::matrix_b, 16, 16, 8, wmma::precision::tf32, wmma::col_major> bf[2];
#pragma unroll
                for (int n = 0; n < 2; n++)
                    wmma::load_matrix_sync(bf[n], Bs + (size_t)(wn * 32 + n * 16) * BK + kk, BK);
#pragma unroll
                for (int m = 0; m < 4; m++)
#pragma unroll
                    for (int n = 0; n < 2; n++)
                        wmma::mma_sync(acc[m][n], af[m], bf[n], acc[m][n]);
            } else {
                wmma::fragment<wmma::matrix_b, 16, 16, 8, wmma::precision::tf32, wmma::row_major> bf[2];
#pragma unroll
                for (int n = 0; n < 2; n++)
                    wmma::load_matrix_sync(bf[n], Bs + (size_t)kk * BN + wn * 32 + n * 16, BN);
#pragma unroll
                for (int m = 0; m < 4; m++)
#pragma unroll
                    for (int n = 0; n < 2; n++)
                        wmma::mma_sync(acc[m][n], af[m], bf[n], acc[m][n]);
            }
        }
        __syncthreads();
    }

    // epilogue: stage to smem [128][132], then bounded vector copy
    float* Cs = sm;
#pragma unroll
    for (int m = 0; m < 4; m++)
#pragma unroll
        for (int n = 0; n < 2; n++)
            wmma::store_matrix_sync(Cs + (size_t)(wm * 64 + m * 16) * 132 + (wn * 32 + n * 16),
                                    acc[m][n], 132, wmma::mem_row_major);
    __syncthreads();
#pragma unroll
    for (int it = 0; it < 64; it++) {     // 64*256 = 16384 = full 128x128 tile
        int idx = it * 256 + tid;
        int r = idx >> 7, c = idx & 127;
        int gr = row0 + r, gc = col0 + c;
        if (gr < M && gc < N) {
            float v = Cs[(size_t)r * 132 + c];
            if (bias)   v += bias[gc];
            if (addvec) v += addvec[gc];
            if (res)    v += res[(size_t)gr * ldc + gc];
            if (EPI == 1) v = 0.5f * v * (1.0f + erff(v * 0.70710678118654752f));
            C[(size_t)gr * ldc + gc] = v;
        }
    }
}

template<int EPI>
__global__ void __launch_bounds__(256, 2)
gemm_tf32_k(const float* __restrict__ A, int lda, const float* __restrict__ B, int ldb,
            const float* __restrict__ bias, const float* __restrict__ res,
            float* __restrict__ C, int ldc, int M, int N, int K) {
    gemm_core<false, EPI>(A, lda, B, ldb, bias, res, C, ldc, M, N, K,
                          blockIdx.y * BM, blockIdx.x * BN, nullptr);
}

__global__ void __launch_bounds__(256, 2)
gemm_bt_k(const float* __restrict__ A, int lda, const float* __restrict__ B, int ldb,
          const float* __restrict__ bias, float* __restrict__ C, int ldc,
          int M, int N, int K) {
    gemm_core<true, 0>(A, lda, B, ldb, bias, nullptr, C, ldc, M, N, K,
                       blockIdx.y * BM, blockIdx.x * BN, nullptr);
}

// scores(z) = Q_z @ K_z^T    z = h*nseg + t
__global__ void __launch_bounds__(256, 2)
qk_tf32(const float* __restrict__ qkv, float* __restrict__ scores, int seg, int nseg) {
    int z = blockIdx.z;
    int h = z / nseg, t = z - h * nseg;
    const float* Qb = qkv + (size_t)t * seg * QKVW + h * DHEAD;
    gemm_core<true, 0>(Qb, QKVW, Qb + 768, QKVW, nullptr, nullptr,
                       scores + (size_t)z * seg * seg, seg,
                       seg, seg, DHEAD, blockIdx.y * BM, blockIdx.x * BN, nullptr);
}

// O(z) = P_z @ V_z (+vmean broadcast), writes into o[tok][h*64+c]
__global__ void __launch_bounds__(256, 2)
av_tf32(const float* __restrict__ scores, const float* __restrict__ qkv,
        const float* __restrict__ vmean, float* __restrict__ o, int seg, int nseg) {
    int z = blockIdx.z;
    int h = z / nseg, t = z - h * nseg;
    gemm_core<false, 0>(scores + (size_t)z * seg * seg, seg,
                        qkv + (size_t)t * seg * QKVW + 1536 + h * DHEAD, QKVW,
                        nullptr, nullptr,
                        o + (size_t)t * seg * DMODEL + h * DHEAD, DMODEL,
                        seg, DHEAD, seg, blockIdx.y * BM, 0,
                        vmean ? vmean + (size_t)z * DHEAD : nullptr);
}

// ---------------- softmax (register-cached, 1R + 1W) ----------------
__global__ void softmax_kernel(float* __restrict__ scores, int seg) {
    float* row = scores + (size_t)blockIdx.x * seg;
    const int tid = threadIdx.x;
    __shared__ float sh[8];
    float rv[7];
    int cnt = 0;
    float m = -1e30f;
    for (int i = tid; i < seg; i += 256) {
        float v = row[i];
        rv[cnt++] = v;
        m = fmaxf(m, v);
    }
#pragma unroll
    for (int o = 16; o; o >>= 1) m = fmaxf(m, __shfl_xor_sync(0xffffffffu, m, o));
    if ((tid & 31) == 0) sh[tid >> 5] = m;
    __syncthreads();
    if (tid < 32) {
        float v = (tid < 8) ? sh[tid] : -1e30f;
#pragma unroll
        for (int o = 4; o; o >>= 1) v = fmaxf(v, __shfl_xor_sync(0xffffffffu, v, o));
        if (tid == 0) sh[0] = v;
    }
    __syncthreads();
    m = sh[0];
    __syncthreads();
    float s = 0.f;
#pragma unroll
    for (int j = 0; j < 7; j++) {
        if (j < cnt) {
            float e = __expf((rv[j] - m) * SCALE_);
            rv[j] = e;
            s += e;
        }
    }
#pragma unroll
    for (int o = 16; o; o >>= 1) s += __shfl_xor_sync(0xffffffffu, s, o);
    if ((tid & 31) == 0) sh[tid >> 5] = s;
    __syncthreads();
    if (tid < 32) {
        float v = (tid < 8) ? sh[tid] : 0.f;
#pragma unroll
        for (int o = 4; o; o >>= 1) v += __shfl_xor_sync(0xffffffffu, v, o);
        if (tid == 0) sh[0] = v;
    }
    __syncthreads();
    float inv = 1.0f / sh[0];
    cnt = 0;
    for (int i = tid; i < seg; i += 256) row[i] = rv[cnt++] * inv;
}

// ---------------- V mean per (head, frame) ----------------
__global__ void vmean_kernel(const float* __restrict__ qkv, float* __restrict__ vmean) {
    int z = blockIdx.x;
    int h = z >> 3, t = z & 7;
    int d = threadIdx.x;
    const float* base = qkv + (size_t)t * NSEQ * QKVW + 1536 + h * DHEAD + d;
    float s = 0.f;
    for (int n = 0; n < NSEQ; n++) s += base[(size_t)n * QKVW];
    vmean[z * DHEAD + d] = s * (1.0f / (float)NSEQ);
}

// ---------------- LayerNorm over 768, float4 (192 threads) ----------------
__global__ void layernorm_kernel(const float* __restrict__ X, const float* __restrict__ g,
                                 const float* __restrict__ b, float* __restrict__ Y) {
    const int row = blockIdx.x;
    const int tid = threadIdx.x;   // 0..191
    __shared__ float sh[8];
    float4 v = *(const float4*)(X + (size_t)row * DMODEL + tid * 4);
    float s = v.x + v.y + v.z + v.w;
#pragma unroll
    for (int o = 16; o; o >>= 1) s += __shfl_xor_sync(0xffffffffu, s, o);
    if ((tid & 31) == 0) sh[tid >> 5] = s;
    __syncthreads();
    if (tid < 32) {
        float t2 = (tid < 6) ? sh[tid] : 0.f;
#pragma unroll
        for (int o = 4; o; o >>= 1) t2 += __shfl_xor_sync(0xffffffffu, t2, o);
        if (tid == 0) sh[0] = t2;
    }
    __syncthreads();
    float mu = sh[0] * (1.0f / (float)DMODEL);
    __syncthreads();
    float dx = v.x - mu, dy = v.y - mu, dz = v.z - mu, dw = v.w - mu;
    s = dx * dx + dy * dy + dz * dz + dw * dw;
#pragma unroll
    for (int o = 16; o; o >>= 1) s += __shfl_xor_sync(0xffffffffu, s, o);
    if ((tid & 31) == 0) sh[tid >> 5] = s;
    __syncthreads();
    if (tid < 32) {
        float t2 = (tid < 6) ? sh[tid] : 0.f;
#pragma unroll
        for (int o = 4; o; o >>= 1) t2 += __shfl_xor_sync(0xffffffffu, t2, o);
        if (tid == 0) sh[0] = t2;
    }
    __syncthreads();
    float rstd = rsqrtf(sh[0] * (1.0f / (float)DMODEL) + 1e-5f);
    float4 gg = *(const float4*)(g + tid * 4);
    float4 bb = *(const float4*)(b + tid * 4);
    float4 out;
    out.x = dx * rstd * gg.x + bb.x;
    out.y = dy * rstd * gg.y + bb.y;
    out.z = dz * rstd * gg.z + bb.z;
    out.w = dw * rstd * gg.w + bb.w;
    *(float4*)(Y + (size_t)row * DMODEL + tid * 4) = out;
}

// ---------------- launch ----------------
extern "C" void kernel_launch(void* const* d_in, const int* in_sizes, int n_in,
                              void* d_out, int out_size) {
    (void)in_sizes; (void)n_in; (void)out_size;
    float* ws = nullptr;
    cudaGetSymbolAddress((void**)&ws, g_ws);

    float* patch  = ws + WS_PATCH;
    float* emb    = ws + WS_EMB;
    float* h      = ws + WS_H;
    float* a      = ws + WS_A;
    float* qkv    = ws + WS_QKV;
    float* scores = ws + WS_SCORES;
    float* o      = ws + WS_O;
    float* mlp    = ws + WS_MLP;
    float* vmean  = ws + WS_VMEAN;

    const float* x      = (const float*)d_in[0];
    const float* Wp     = (const float*)d_in[1];
    const float* bp     = (const float*)d_in[2];
    const float* cls    = (const float*)d_in[3];
    const float* pos    = (const float*)d_in[4];
    const float* ln1_g  = (const float*)d_in[5];
    const float* ln1_b  = (const float*)d_in[6];
    const float* qkv_w  = (const float*)d_in[7];
    const float* qkv_b  = (const float*)d_in[8];
    const float* proj_w = (const float*)d_in[9];
    const float* proj_b = (const float*)d_in[10];
    const float* ln2_g  = (const float*)d_in[11];
    const float* ln2_b  = (const float*)d_in[12];
    const float* fc1_w  = (const float*)d_in[13];
    const float* fc1_b  = (const float*)d_in[14];
    const float* fc2_w  = (const float*)d_in[15];
    const float* fc2_b  = (const float*)d_in[16];
    const float* lnf_g  = (const float*)d_in[17];
    const float* lnf_b  = (const float*)d_in[18];

    // opt-in >48KB dynamic smem for all GEMM instantiations
    cudaFuncSetAttribute(gemm_tf32_k<0>, cudaFuncAttributeMaxDynamicSharedMemorySize, SMEM_GEMM_BYTES);
    cudaFuncSetAttribute(gemm_tf32_k<1>, cudaFuncAttributeMaxDynamicSharedMemorySize, SMEM_GEMM_BYTES);
    cudaFuncSetAttribute(gemm_bt_k,      cudaFuncAttributeMaxDynamicSharedMemorySize, SMEM_GEMM_BYTES);
    cudaFuncSetAttribute(qk_tf32,        cudaFuncAttributeMaxDynamicSharedMemorySize, SMEM_GEMM_BYTES);
    cudaFuncSetAttribute(av_tf32,        cudaFuncAttributeMaxDynamicSharedMemorySize, SMEM_GEMM_BYTES);

    // patch embed
    gather_patches<<<(1568 * 768 + 255) / 256, 256>>>(x, patch);
    gemm_bt_k<<<dim3(6, 13), 256, SMEM_GEMM_BYTES>>>(patch, 768, Wp, 768, bp, emb, 768,
                                                     1568, 768, 768);
    assemble_h<<<(NTOK * DMODEL + 255) / 256, 256>>>(emb, cls, pos, h);

    for (int i = 0; i < 12; i++) {
        // ---- attention ----
        layernorm_kernel<<<NTOK, 192>>>(h, ln1_g + i * DMODEL, ln1_b + i * DMODEL, a);
        gemm_tf32_k<0><<<dim3(18, 13), 256, SMEM_GEMM_BYTES>>>(
            a, DMODEL, qkv_w + (size_t)i * DMODEL * QKVW, QKVW,
            qkv_b + i * QKVW, nullptr, qkv, QKVW, NTOK, QKVW, DMODEL);

        if ((i & 1) == 0) {
            // divided space-time: spatial attention per frame + V-mean broadcast
            vmean_kernel<<<NHEAD * T_FR, DHEAD>>>(qkv, vmean);
            qk_tf32<<<dim3(2, 2, NHEAD * T_FR), 256, SMEM_GEMM_BYTES>>>(qkv, scores, NSEQ, T_FR);
            softmax_kernel<<<NHEAD * T_FR * NSEQ, 256>>>(scores, NSEQ);
            av_tf32<<<dim3(1, 2, NHEAD * T_FR), 256, SMEM_GEMM_BYTES>>>(scores, qkv, vmean, o, NSEQ, T_FR);
        } else {
            // joint space-time
            qk_tf32<<<dim3(13, 13, NHEAD), 256, SMEM_GEMM_BYTES>>>(qkv, scores, NTOK, 1);
            softmax_kernel<<<NHEAD * NTOK, 256>>>(scores, NTOK);
            av_tf32<<<dim3(1, 13, NHEAD), 256, SMEM_GEMM_BYTES>>>(scores, qkv, nullptr, o, NTOK, 1);
        }
        // h += proj(o)
        gemm_tf32_k<0><<<dim3(6, 13), 256, SMEM_GEMM_BYTES>>>(
            o, DMODEL, proj_w + (size_t)i * DMODEL * DMODEL, DMODEL,
            proj_b + i * DMODEL, h, h, DMODEL, NTOK, DMODEL, DMODEL);

        // ---- mlp ----
        layernorm_kernel<<<NTOK, 192>>>(h, ln2_g + i * DMODEL, ln2_b + i * DMODEL, a);
        gemm_tf32_k<1><<<dim3(24, 13), 256, SMEM_GEMM_BYTES>>>(
            a, DMODEL, fc1_w + (size_t)i * DMODEL * DMLP, DMLP,
            fc1_b + i * DMLP, nullptr, mlp, DMLP, NTOK, DMLP, DMODEL);
        gemm_tf32_k<0><<<dim3(6, 13), 256, SMEM_GEMM_BYTES>>>(
            mlp, DMLP, fc2_w + (size_t)i * DMLP * DMODEL, DMODEL,
            fc2_b + i * DMODEL, h, h, DMODEL, NTOK, DMODEL, DMLP);
    }

    layernorm_kernel<<<NTOK, 192>>>(h, lnf_g, lnf_b, (float*)d_out);
}